// round 4
// baseline (speedup 1.0000x reference)
#include <cuda_runtime.h>

#define TPB 256
#define NWARP 8
#define LOCW 12

// Pre-transposed alpha_w: g_awT[h*64 + c2] = alpha_w[c2*64 + h]
__device__ float g_awT[64 * 64];

__global__ void prep_transpose(const float* __restrict__ aw) {
    int i = blockIdx.x * blockDim.x + threadIdx.x;
    if (i < 4096) {
        int hh = i >> 6, c2 = i & 63;
        g_awT[i] = aw[c2 * 64 + hh];
    }
}

// Shared layout (floats):
//   [0      .. 9504)  sh_x   : 32 ch * (3 rows * 99 cols) staged input (stride 297)
//                              aliased as sh_out (96*65) after phase 2
//   [9504   .. 15648) sh_h   : 96 locations * 64 hidden
//   [15648  .. 15744) sh_proj: 96
//   [15744  .. 15840) sh_pb  : 96  (phi_b . patch term)
//   [15840  .. 15968) sh_hist: 8 warps * 16 bins (int)  == 128 slots
#define SMEM_FLOATS (15840 + 128)
#define SMEM_BYTES  (SMEM_FLOATS * 4)

__global__ __launch_bounds__(TPB, 3)
void sac_kernel(const float* __restrict__ x,
                const float* __restrict__ fc1_w, const float* __restrict__ fc1_b,
                const float* __restrict__ alpha_b,
                const float* __restrict__ phi_w, const float* __restrict__ phi_b,
                const float* __restrict__ bn_gamma, const float* __restrict__ bn_beta,
                const float* __restrict__ bn_mean, const float* __restrict__ bn_var,
                float* __restrict__ out)
{
    extern __shared__ float smem[];
    float* sh_x    = smem;
    float* sh_h    = smem + 9504;
    float* sh_proj = smem + 15648;
    float* sh_pb   = smem + 15744;
    int*   sh_hist = (int*)(smem + 15840);
    float* sh_out  = smem;   // aliases sh_x after phase 2 (guarded by __syncthreads)

    const int y    = blockIdx.x;   // output row 0..95
    const int b    = blockIdx.y;   // batch 0..3
    const int tid  = threadIdx.x;
    const int warp = tid >> 5;
    const int lane = tid & 31;

    // ---------------- phase 0: stage x rows (y-1, y, y+1), zero padded ----------------
    const float* xb = x + (size_t)b * 32 * 9216;
    for (int i = tid; i < 32 * 3 * 98; i += TPB) {
        int c   = i / 294;
        int rem = i - c * 294;
        int r   = rem / 98;
        int cc  = rem - r * 98;          // cc corresponds to gx = cc-1
        int gy  = y + r - 1;
        int gx  = cc - 1;
        float v = 0.f;
        if ((unsigned)gy < 96u && (unsigned)gx < 96u)
            v = xb[(c * 96 + gy) * 96 + gx];
        sh_x[c * 297 + r * 99 + cc] = v;
    }
    __syncthreads();

    // ---------------- phase 1: stats + fc1 hidden, warp-per-location ----------------
    const float inv288 = 1.0f / 288.0f;
    const float invPr  = 1.0f / (288.0f + 1e-6f);   // reference: counts / (ckk + 1e-6)

    // lane-invariant weights hoisted out of the li loop
    float pbw[9];
    #pragma unroll
    for (int k = 0; k < 9; k++) pbw[k] = __ldg(&phi_b[lane * 9 + k]);
    float w1c[5], w1c2[5];
    #pragma unroll
    for (int k = 0; k < 5; k++) {
        w1c[k]  = __ldg(&fc1_w[lane * 5 + k]);
        w1c2[k] = __ldg(&fc1_w[(lane + 32) * 5 + k]);
    }
    const float b1  = __ldg(&fc1_b[lane]);
    const float b1b = __ldg(&fc1_b[lane + 32]);

    for (int li = warp; li < 96; li += NWARP) {
        // lane = channel; 3x3 taps. sh col (li + kc) == gx = li + kc - 1
        float v[9];
        const float* base = sh_x + lane * 297 + li;
        #pragma unroll
        for (int r = 0; r < 3; r++)
            #pragma unroll
            for (int kc = 0; kc < 3; kc++)
                v[r * 3 + kc] = base[r * 99 + kc];

        float s1 = 0.f, mn = v[0], mx = v[0];
        #pragma unroll
        for (int k = 0; k < 9; k++) {
            s1 += v[k];
            mn = fminf(mn, v[k]);
            mx = fmaxf(mx, v[k]);
        }
        #pragma unroll
        for (int o = 16; o; o >>= 1) {
            s1 += __shfl_xor_sync(0xffffffffu, s1, o);
            mn = fminf(mn, __shfl_xor_sync(0xffffffffu, mn, o));
            mx = fmaxf(mx, __shfl_xor_sync(0xffffffffu, mx, o));
        }
        float mu = s1 * inv288;

        float sd2 = 0.f, sd3 = 0.f, sd4 = 0.f, pbp = 0.f;
        #pragma unroll
        for (int k = 0; k < 9; k++) {
            float d  = v[k] - mu;
            float d2 = d * d;
            sd2 += d2; sd3 += d2 * d; sd4 += d2 * d2;
            pbp += pbw[k] * v[k];
        }
        #pragma unroll
        for (int o = 16; o; o >>= 1) {
            sd2 += __shfl_xor_sync(0xffffffffu, sd2, o);
            sd3 += __shfl_xor_sync(0xffffffffu, sd3, o);
            sd4 += __shfl_xor_sync(0xffffffffu, sd4, o);
            pbp += __shfl_xor_sync(0xffffffffu, pbp, o);
        }
        float var   = sd2 * inv288;
        float sigma = sqrtf(var + 1e-6f);
        float q     = sigma + 1e-6f;
        float iq    = 1.0f / q;
        float iq2   = iq * iq;
        float gam   = sd3 * inv288 * iq2 * iq;
        float kap   = sd4 * inv288 * iq2 * iq2 - 3.0f;

        // histogram entropy (binning arithmetic bit-matches reference)
        int* hist = sh_hist + warp * 16;
        if (lane < 16) hist[lane] = 0;
        __syncwarp();
        float denom = (mx - mn) + 1e-6f;
        #pragma unroll
        for (int k = 0; k < 9; k++) {
            float pn = (v[k] - mn) / denom;    // IEEE div, matches reference
            int bi = (int)(pn * 15.0f);        // truncation == astype(int32)
            bi = max(0, min(15, bi));
            atomicAdd(&hist[bi], 1);
        }
        __syncwarp();
        float ent = 0.f;
        if (lane < 16) {
            float prob = (float)hist[lane] * invPr;
            ent = -prob * logf(prob + 1e-9f);
        }
        __syncwarp();   // reads done before next iteration re-zeroes
        #pragma unroll
        for (int o = 16; o; o >>= 1)
            ent += __shfl_xor_sync(0xffffffffu, ent, o);

        // fc1 + relu; lane computes h[lane] and h[lane+32]
        float ss[5] = {mu, sigma, gam, kap, ent};
        float h0 = b1;
        float h1 = b1b;
        #pragma unroll
        for (int k = 0; k < 5; k++) {
            h0 += w1c[k]  * ss[k];
            h1 += w1c2[k] * ss[k];
        }
        sh_h[li * 64 + lane]      = fmaxf(h0, 0.f);
        sh_h[li * 64 + lane + 32] = fmaxf(h1, 0.f);
        if (lane == 0) sh_pb[li] = pbp;
    }
    __syncthreads();

    // ---------------- phase 2: phi GEMM (t = phi_w^T @ patch) + proj ----------------
    // lane = h-pair (h = 2*lane, 2*lane+1); warp covers 12 locations x0..x0+11
    const int x0 = warp * LOCW;
    float acc0[LOCW], acc1[LOCW];
    #pragma unroll
    for (int l = 0; l < LOCW; l++) { acc0[l] = 0.f; acc1[l] = 0.f; }

    const float2* pw = (const float2*)phi_w;   // phi_w[j*64 + h], float2 idx = j*32 + lane
    for (int c = 0; c < 32; c++) {
        #pragma unroll
        for (int kh = 0; kh < 3; kh++) {
            const float* rp = sh_x + c * 297 + kh * 99 + x0;
            float p[LOCW + 2];
            #pragma unroll
            for (int t = 0; t < LOCW + 2; t++) p[t] = rp[t];   // uniform broadcasts
            int jb = c * 9 + kh * 3;
            #pragma unroll
            for (int kw = 0; kw < 3; kw++) {
                float2 w = __ldg(&pw[(jb + kw) * 32 + lane]);
                #pragma unroll
                for (int l = 0; l < LOCW; l++) {
                    acc0[l] += w.x * p[l + kw];
                    acc1[l] += w.y * p[l + kw];
                }
            }
        }
    }
    // proj[l] = sum_h h[l][h] * t[h][l]  (+ phi_b . patch)
    float pr[LOCW];
    #pragma unroll
    for (int l = 0; l < LOCW; l++) {
        float2 hv = ((const float2*)(sh_h + (x0 + l) * 64))[lane];
        pr[l] = acc0[l] * hv.x + acc1[l] * hv.y;
    }
    #pragma unroll
    for (int o = 16; o; o >>= 1)
        #pragma unroll
        for (int l = 0; l < LOCW; l++)
            pr[l] += __shfl_xor_sync(0xffffffffu, pr[l], o);
    if (lane == 0) {
        #pragma unroll
        for (int l = 0; l < LOCW; l++)
            sh_proj[x0 + l] = pr[l] + sh_pb[x0 + l];
    }
    __syncthreads();   // also retires all sh_x reads before sh_out alias writes

    // ---------------- phase 3: alpha GEMM + BN + SiLU -> sh_out (transpose buffer) ----
    const int c20 = 2 * lane;
    float a0[LOCW], a1[LOCW];
    {
        float ab0 = __ldg(&alpha_b[c20]), ab1 = __ldg(&alpha_b[c20 + 1]);
        #pragma unroll
        for (int l = 0; l < LOCW; l++) { a0[l] = ab0; a1[l] = ab1; }
    }
    const float2* awT = (const float2*)g_awT;  // awT[h*64 + c2]
    for (int hh = 0; hh < 64; hh += 4) {
        float2 w0 = __ldg(&awT[(hh + 0) * 32 + lane]);
        float2 w1 = __ldg(&awT[(hh + 1) * 32 + lane]);
        float2 w2 = __ldg(&awT[(hh + 2) * 32 + lane]);
        float2 w3 = __ldg(&awT[(hh + 3) * 32 + lane]);
        #pragma unroll
        for (int l = 0; l < LOCW; l++) {
            const float4 hv = *(const float4*)(sh_h + (x0 + l) * 64 + hh);
            a0[l] += w0.x * hv.x + w1.x * hv.y + w2.x * hv.z + w3.x * hv.w;
            a1[l] += w0.y * hv.x + w1.y * hv.y + w2.y * hv.z + w3.y * hv.w;
        }
    }
    {
        float inv0 = __ldg(&bn_gamma[c20])     / sqrtf(__ldg(&bn_var[c20])     + 1e-5f);
        float inv1 = __ldg(&bn_gamma[c20 + 1]) / sqrtf(__ldg(&bn_var[c20 + 1]) + 1e-5f);
        float m0 = __ldg(&bn_mean[c20]), m1 = __ldg(&bn_mean[c20 + 1]);
        float be0 = __ldg(&bn_beta[c20]), be1 = __ldg(&bn_beta[c20 + 1]);
        #pragma unroll
        for (int l = 0; l < LOCW; l++) {
            float pj = sh_proj[x0 + l];
            float y0 = (a0[l] * pj - m0) * inv0 + be0;
            float y1 = (a1[l] * pj - m1) * inv1 + be1;
            sh_out[(x0 + l) * 65 + c20]     = y0 / (1.0f + __expf(-y0));
            sh_out[(x0 + l) * 65 + c20 + 1] = y1 / (1.0f + __expf(-y1));
        }
    }
    __syncthreads();

    // ---------------- phase 4: coalesced global write ----------------
    float* ob = out + (size_t)b * 64 * 9216 + y * 96;
    for (int i = tid; i < 6144; i += TPB) {
        int c2 = i / 96;
        int xx = i - c2 * 96;
        ob[(size_t)c2 * 9216 + xx] = sh_out[xx * 65 + c2];
    }
}

extern "C" void kernel_launch(void* const* d_in, const int* in_sizes, int n_in,
                              void* d_out, int out_size) {
    // ---- Resolve inputs by SIZE (robust to metadata ordering), with positional fallback ----
    int ix = -1, ifc1w = -1, iaw = -1, ipw = -1, ipb = -1;
    int idx64[8]; int n64 = 0;
    for (int i = 0; i < n_in; i++) {
        switch (in_sizes[i]) {
            case 1179648: ix    = i; break;
            case 18432:   ipw   = i; break;
            case 4096:    iaw   = i; break;
            case 320:     ifc1w = i; break;
            case 288:     ipb   = i; break;
            case 64:      if (n64 < 8) idx64[n64++] = i; break;
            default: break;
        }
    }
    int ifc1b, iab, ibg, ibb, ibm, ibv;
    if (ix < 0 || ipw < 0 || iaw < 0 || ifc1w < 0 || ipb < 0 || n64 < 6) {
        // Fallback: declaration order per reference setup_inputs()
        ix = 0; ifc1w = 1; ifc1b = 2; iaw = 3; iab = 4; ipw = 5; ipb = 6;
        ibg = 7; ibb = 8; ibm = 9; ibv = 10;
    } else if (ix == 0) {
        // declaration order: fc1_b, alpha_b, bn_gamma, bn_beta, bn_mean, bn_var
        ifc1b = idx64[0]; iab = idx64[1]; ibg = idx64[2];
        ibb   = idx64[3]; ibm = idx64[4]; ibv = idx64[5];
    } else {
        // alphabetical: alpha_b, bn_beta, bn_gamma, bn_mean, bn_var, fc1_b
        iab   = idx64[0]; ibb = idx64[1]; ibg = idx64[2];
        ibm   = idx64[3]; ibv = idx64[4]; ifc1b = idx64[5];
    }

    const float* x        = (const float*)d_in[ix];
    const float* fc1_w    = (const float*)d_in[ifc1w];
    const float* fc1_b    = (const float*)d_in[ifc1b];
    const float* alpha_w  = (const float*)d_in[iaw];
    const float* alpha_b  = (const float*)d_in[iab];
    const float* phi_w    = (const float*)d_in[ipw];
    const float* phi_b    = (const float*)d_in[ipb];
    const float* bn_gamma = (const float*)d_in[ibg];
    const float* bn_beta  = (const float*)d_in[ibb];
    const float* bn_mean  = (const float*)d_in[ibm];
    const float* bn_var   = (const float*)d_in[ibv];
    float* out = (float*)d_out;

    cudaFuncSetAttribute(sac_kernel, cudaFuncAttributeMaxDynamicSharedMemorySize, SMEM_BYTES);

    prep_transpose<<<16, 256>>>(alpha_w);
    dim3 grid(96, 4);
    sac_kernel<<<grid, TPB, SMEM_BYTES>>>(x, fc1_w, fc1_b, alpha_b, phi_w, phi_b,
                                          bn_gamma, bn_beta, bn_mean, bn_var, out);
}